// round 6
// baseline (speedup 1.0000x reference)
#include <cuda_runtime.h>
#include <cuda_fp16.h>
#include <math.h>

namespace {

constexpr int DKP = 28;              // padded factor dim
constexpr int NDIM = 2 * DKP;        // 56 floats per node/row (224B)
constexpr int HS   = 28;             // half2 stride per node in fp16 mirror
constexpr int TOTAL_NODES = 180000;
constexpr int TOTAL_ROWS  = 270000;
constexpr int TOTAL_COLS  = 180000;
constexpr int TOTAL_EDGES = 3800000;
constexpr int OUT_ROWS = 90000;
constexpr int SCAN_ELEMS = 8192;     // per block (1024 thr x 8)
constexpr int SCAN_NBLK = (TOTAL_ROWS + SCAN_ELEMS - 1) / SCAN_ELEMS; // 33
constexpr int NB_INIT = (TOTAL_NODES * 2 + 255) / 256;  // 1407
constexpr int NB_HIST = (TOTAL_EDGES + 255) / 256;      // 14844

__constant__ int c_EOFF[9] = {0,1000000,2000000,2300000,2600000,2900000,3200000,3500000,3800000};
__constant__ int c_ROFF[9] = {0,60000,90000,120000,150000,180000,210000,240000,270000};
__constant__ int c_COFF[9] = {0,30000,90000,105000,120000,135000,150000,165000,180000};
__constant__ int c_TOFF[9] = {0,60000,90000,105000,120000,135000,150000,165000,180000};
__constant__ int c_SRC[8]  = {0,1,1,1,1,1,1,1};
__constant__ int c_DST[8]  = {1,0,2,3,4,5,6,7};

__device__ float    g_emb [(size_t)TOTAL_NODES * NDIM + 16]; // fp32 master
__device__ unsigned g_embh[(size_t)TOTAL_NODES * HS];        // fp16 mirror: half2(k0[d],k1[d])
__device__ float    g_z   [(size_t)TOTAL_ROWS  * NDIM];      // z rows: [2d+k] interleaved
__device__ float    g_p   [TOTAL_ROWS * 2];
__device__ __half   g_qh  [TOTAL_COLS * 2];                  // fp16 q, pair-packed
__device__ float    g_r   [TOTAL_ROWS * 2];
__device__ int      g_rowcnt[TOTAL_ROWS];        // zeroed by k_fill after use
__device__ int      g_scanflag[SCAN_NBLK];       // zeroed by k_fill after use
__device__ int      g_rowptr[TOTAL_ROWS + 1];
__device__ int      g_blocksum[SCAN_NBLK];
__device__ int      g_rank  [TOTAL_EDGES];
__device__ int      g_colidx[TOTAL_EDGES];

struct Ptrs {
    const int*   edge[8];
    const float* embin[8];
    const float* Wtk;
    const float* at;
    const float* W;
    const float* q_rela;
};

__device__ __forceinline__ int find_seg8(const int* off, int x) {
    int e = 0;
    #pragma unroll
    for (int i = 1; i < 8; i++) e += (x >= off[i]);
    return e;
}

__device__ __forceinline__ float fast_tanh(float x) {
    float y;
    asm("tanh.approx.f32 %0, %1;" : "=f"(y) : "f"(x));
    return y;
}

__device__ __forceinline__ float dot25(const float* v, const float* a) {
    float s = 0.f;
    #pragma unroll
    for (int d = 0; d < 25; d++) s += v[d] * __ldg(&a[d]);
    return s;
}

__device__ __forceinline__ void write_pq(int t, int n, int k, const float* vec, const float* at) {
    if (t == 0) {
        g_p [(c_ROFF[0] + n) * 2 + k] = dot25(vec, at + (0 * 2 + k) * 50);
        g_qh[(c_COFF[1] + n) * 2 + k] = __float2half(dot25(vec, at + (1 * 2 + k) * 50 + 25));
    } else if (t == 1) {
        #pragma unroll
        for (int e = 1; e < 8; e++)
            g_p[(c_ROFF[e] + n) * 2 + k] = dot25(vec, at + (e * 2 + k) * 50);
        g_qh[(c_COFF[0] + n) * 2 + k] = __float2half(dot25(vec, at + (0 * 2 + k) * 50 + 25));
    } else {
        g_qh[(c_COFF[t] + n) * 2 + k] = __float2half(dot25(vec, at + (t * 2 + k) * 50 + 25));
    }
}

__device__ __forceinline__ void write_mirror(int node, int k, const float* vec) {
    __half* h = (__half*)g_embh;
    #pragma unroll
    for (int d = 0; d < 25; d++) h[(size_t)node * 2 * HS + 2 * d + k] = __float2half(vec[d]);
}

// ---------------- fused prologue: init (blocks < NB_INIT) + hist (rest) ----------
__global__ void __launch_bounds__(256) k_pre(Ptrs P) {
    __shared__ float Wsh[2][2][50 * 25];
    if (blockIdx.x < NB_INIT) {
        int base_slot = blockIdx.x * 256;
        int node0 = base_slot >> 1;
        int nlast = (base_slot + 255) >> 1;
        if (nlast > TOTAL_NODES - 1) nlast = TOTAL_NODES - 1;
        int t0 = find_seg8(c_TOFF, node0);
        int t1 = find_seg8(c_TOFF, nlast);
        for (int i = threadIdx.x; i < 2 * 50 * 25; i += 256) {
            Wsh[0][0][i] = P.Wtk[(size_t)t0 * 2 * 50 * 25 + i];
            Wsh[1][0][i] = P.Wtk[(size_t)t1 * 2 * 50 * 25 + i];
        }
        __syncthreads();
        int slot = base_slot + threadIdx.x;
        if (slot >= TOTAL_NODES * 2) return;
        int node = slot >> 1, k = slot & 1;
        int t = find_seg8(c_TOFF, node);
        int sel = (t == t0) ? 0 : 1;
        const float* x = P.embin[t] + (size_t)(node - c_TOFF[t]) * 50;
        const float* w = &Wsh[sel][k][0];
        float out[25];
        #pragma unroll
        for (int f = 0; f < 25; f++) out[f] = 0.f;
        for (int d = 0; d < 50; d++) {
            float xd = __ldg(&x[d]);
            #pragma unroll
            for (int f = 0; f < 25; f++) out[f] += xd * w[d * 25 + f];
        }
        float nrm = 0.f;
        #pragma unroll
        for (int f = 0; f < 25; f++) {
            float s = out[f];
            s = (s >= 0.f) ? s : 0.2f * s;
            out[f] = s;
            nrm += s * s;
        }
        float inv = 1.f / fmaxf(sqrtf(nrm), 1e-12f);
        #pragma unroll
        for (int f = 0; f < 25; f++) out[f] *= inv;
        float* dst = g_emb + (size_t)node * NDIM + k * DKP;
        #pragma unroll
        for (int f = 0; f < 25; f++) dst[f] = out[f];
        dst[25] = 0.f; dst[26] = 0.f; dst[27] = 0.f;
        write_mirror(node, k, out);
        write_pq(t, node - c_TOFF[t], k, out, P.at);
    } else {
        int j = (blockIdx.x - NB_INIT) * 256 + threadIdx.x;
        if (j >= TOTAL_EDGES) return;
        int e = find_seg8(c_EOFF, j);
        int le = j - c_EOFF[e];
        int u = P.edge[e][le];
        g_rank[j] = atomicAdd(&g_rowcnt[c_ROFF[e] + u], 1);
    }
}

// ---------------- chained scan (33 blocks, all co-resident) -----------------------
__global__ void __launch_bounds__(1024, 2) k_scan() {
    __shared__ int sh[1024];
    __shared__ int sh_prefix;
    int bid = blockIdx.x, tid = threadIdx.x;
    int base = bid * SCAN_ELEMS + tid * 8;
    int v[8];
    #pragma unroll
    for (int u = 0; u < 8; u++) {
        int i = base + u;
        v[u] = (i < TOTAL_ROWS) ? g_rowcnt[i] : 0;
    }
    int tsum = 0;
    #pragma unroll
    for (int u = 0; u < 8; u++) tsum += v[u];
    sh[tid] = tsum;
    __syncthreads();
    #pragma unroll
    for (int off = 1; off < 1024; off <<= 1) {
        int t = (tid >= off) ? sh[tid - off] : 0;
        __syncthreads();
        sh[tid] += t;
        __syncthreads();
    }
    int excl = sh[tid] - tsum;
    int total = sh[1023];
    if (tid == 0) {
        int prefix = 0;
        if (bid > 0) {
            volatile int* flag = (volatile int*)g_scanflag;
            while (flag[bid - 1] == 0) {}
            prefix = *((volatile int*)&g_blocksum[bid - 1]);
        }
        *((volatile int*)&g_blocksum[bid]) = prefix + total;
        __threadfence();
        *((volatile int*)&g_scanflag[bid]) = 1;
        sh_prefix = prefix;
    }
    __syncthreads();
    int p = sh_prefix + excl;
    #pragma unroll
    for (int u = 0; u < 8; u++) {
        int i = base + u;
        if (i < TOTAL_ROWS) g_rowptr[i] = p;
        p += v[u];
    }
    if (bid == SCAN_NBLK - 1 && tid == 1023) g_rowptr[TOTAL_ROWS] = sh_prefix + total;
}

// ---------------- fill colidx; also reset rowcnt/scanflags for next launch --------
__global__ void k_fill(Ptrs P) {
    int j = blockIdx.x * blockDim.x + threadIdx.x;
    if (j < SCAN_NBLK) g_scanflag[j] = 0;
    if (j < TOTAL_ROWS) g_rowcnt[j] = 0;
    if (j >= TOTAL_EDGES) return;
    int e = find_seg8(c_EOFF, j);
    int le = j - c_EOFF[e];
    int E = c_EOFF[e + 1] - c_EOFF[e];
    const int* ed = P.edge[e];
    int u = ed[le], c = ed[E + le];
    int row = c_ROFF[e] + u;
    g_colidx[g_rowptr[row] + g_rank[j]] = c;
}

// ---------------- warp-per-row: score + exp-weight + aggregate --------------------
// (w,c) staged in shared once per chunk -> broadcast LDS.64, no shfl pairs.
// Writes z/s to g_z interleaved: zr[2d+k].
__global__ void __launch_bounds__(256) k_rowagg() {
    __shared__ float2 wc[8][32];
    int row  = (blockIdx.x * 256 + threadIdx.x) >> 5;
    int lane = threadIdx.x & 31;
    int w_id = (threadIdx.x >> 5);
    if (row >= TOTAL_ROWS) return;
    int e = find_seg8(c_ROFF, row);
    int base = g_rowptr[row];
    int deg  = g_rowptr[row + 1] - base;
    float* zr = g_z + (size_t)row * NDIM;
    if (deg == 0) {
        if (lane < 25) ((float2*)zr)[lane] = make_float2(0.f, 0.f);
        return;
    }
    int coff  = c_COFF[e];
    int nbase = c_TOFF[c_DST[e]];
    float2 pv = ((const float2*)g_p)[row];
    int dlane = (lane < 25) ? lane : 24;

    float s = 0.f;
    float accA = 0.f, accB = 0.f;

    const unsigned* qh32 = (const unsigned*)g_qh;
    for (int i0 = 0; i0 < deg; i0 += 32) {
        int i = i0 + lane;
        int c = 0; float w = 0.f;
        if (i < deg) {
            c = __ldg(&g_colidx[base + i]);
            unsigned qraw = __ldg(&qh32[coff + c]);
            float2 qv = __half22float2(*(const __half2*)&qraw);
            float v = 0.5f * (fmaxf(pv.x + qv.x, 0.f) + fmaxf(pv.y + qv.y, 0.f));
            w = __expf(v);
            s += w;
        }
        wc[w_id][lane] = make_float2(w, __int_as_float(c));
        __syncwarp();
        int nn = deg - i0; if (nn > 32) nn = 32;
        int nn4 = (nn + 3) & ~3;           // padded lanes: w=0, c=0 -> harmless
        for (int j = 0; j < nn4; j += 4) {
            float2 e0 = wc[w_id][j + 0];
            float2 e1 = wc[w_id][j + 1];
            float2 e2 = wc[w_id][j + 2];
            float2 e3 = wc[w_id][j + 3];
            unsigned h0 = __ldg(&g_embh[(size_t)(nbase + __float_as_int(e0.y)) * HS + dlane]);
            unsigned h1 = __ldg(&g_embh[(size_t)(nbase + __float_as_int(e1.y)) * HS + dlane]);
            unsigned h2 = __ldg(&g_embh[(size_t)(nbase + __float_as_int(e2.y)) * HS + dlane]);
            unsigned h3 = __ldg(&g_embh[(size_t)(nbase + __float_as_int(e3.y)) * HS + dlane]);
            float2 f0 = __half22float2(*(const __half2*)&h0);
            float2 f1 = __half22float2(*(const __half2*)&h1);
            float2 f2 = __half22float2(*(const __half2*)&h2);
            float2 f3 = __half22float2(*(const __half2*)&h3);
            accA += e0.x * f0.x; accB += e0.x * f0.y;
            accA += e1.x * f1.x; accB += e1.x * f1.y;
            accA += e2.x * f2.x; accB += e2.x * f2.y;
            accA += e3.x * f3.x; accB += e3.x * f3.y;
        }
        __syncwarp();
    }
    #pragma unroll
    for (int off = 16; off; off >>= 1)
        s += __shfl_xor_sync(0xffffffffu, s, off);
    float invS = 1.f / s;
    if (lane < 25)
        ((float2*)zr)[lane] = make_float2(accA * invS, accB * invS);
}

// ---------------- thread-per-row transform: z'=lrelu(z)@W, r=softmax --------------
__global__ void __launch_bounds__(128) k_trans(Ptrs P) {
    __shared__ float Ws[625];
    __shared__ float qsh[200];
    for (int i = threadIdx.x; i < 625; i += 128) Ws[i] = P.W[i];
    for (int i = threadIdx.x; i < 200; i += 128) qsh[i] = P.q_rela[i];
    __syncthreads();
    int row = blockIdx.x * 128 + threadIdx.x;
    if (row >= TOTAL_ROWS) return;
    int e = find_seg8(c_ROFF, row);
    float* zr = g_z + (size_t)row * NDIM;
    float sc[2];
    #pragma unroll
    for (int k = 0; k < 2; k++) {
        float z[25];
        #pragma unroll
        for (int d = 0; d < 25; d++) {
            float v = zr[2 * d + k];
            z[d] = (v >= 0.f) ? v : 0.2f * v;
        }
        float out[25];
        #pragma unroll
        for (int f = 0; f < 25; f++) out[f] = 0.f;
        #pragma unroll
        for (int d = 0; d < 25; d++) {
            float zd = z[d];
            #pragma unroll
            for (int f = 0; f < 25; f++) out[f] += zd * Ws[d * 25 + f];
        }
        float sk = 0.f;
        #pragma unroll
        for (int f = 0; f < 25; f++) {
            zr[2 * f + k] = out[f];
            sk += fast_tanh(out[f]) * qsh[e * 25 + f];
        }
        sc[k] = sk;
    }
    float mm = fmaxf(sc[0], sc[1]);
    float e0 = __expf(sc[0] - mm), e1 = __expf(sc[1] - mm);
    float inv = 1.f / (e0 + e1);
    ((float2*)g_r)[row] = make_float2(e0 * inv, e1 * inv);
}

// ---------------- ego aggregation + l2 normalize + p/q + mirror refresh -----------
__global__ void __launch_bounds__(256) k_agg(Ptrs P) {
    int slot = blockIdx.x * 256 + threadIdx.x;
    if (slot >= OUT_ROWS * 2) return;
    int node = slot >> 1, k = slot & 1;
    float acc[25];
    float* er = g_emb + (size_t)node * NDIM + k * DKP;
    #pragma unroll
    for (int d = 0; d < 25; d++) acc[d] = er[d];
    if (node < 60000) {                 // type 0: relation 0 only
        float r = g_r[node * 2 + k];
        const float* zz = g_z + (size_t)node * NDIM;
        #pragma unroll
        for (int d = 0; d < 25; d++) acc[d] += r * zz[2 * d + k];
    } else {                            // type 1: relations 1..7
        int n = node - 60000;
        #pragma unroll
        for (int e = 1; e < 8; e++) {
            int row = c_ROFF[e] + n;
            float r = g_r[row * 2 + k];
            const float* zz = g_z + (size_t)row * NDIM;
            #pragma unroll
            for (int d = 0; d < 25; d++) acc[d] += r * zz[2 * d + k];
        }
    }
    float nrm = 0.f;
    #pragma unroll
    for (int d = 0; d < 25; d++) nrm += acc[d] * acc[d];
    float inv = 1.f / fmaxf(sqrtf(nrm), 1e-12f);
    #pragma unroll
    for (int d = 0; d < 25; d++) acc[d] *= inv;
    #pragma unroll
    for (int d = 0; d < 25; d++) er[d] = acc[d];
    write_mirror(node, k, acc);
    int t = (node < 60000) ? 0 : 1;
    write_pq(t, (t == 0) ? node : node - 60000, k, acc, P.at);
}

// ---------------- output: [n, k*25+d] for user then item --------------------------
__global__ void k_out(float* __restrict__ out) {
    int idx = blockIdx.x * blockDim.x + threadIdx.x;
    if (idx >= OUT_ROWS * 50) return;
    int r = idx / 50, c = idx - r * 50;
    int k = c / 25, d = c - k * 25;
    out[idx] = g_emb[(size_t)r * NDIM + k * DKP + d];
}

} // anonymous namespace

extern "C" void kernel_launch(void* const* d_in, const int* in_sizes, int n_in,
                              void* d_out, int out_size) {
    Ptrs P;
    for (int i = 0; i < 8; i++) P.edge[i]  = (const int*)d_in[i];
    for (int i = 0; i < 8; i++) P.embin[i] = (const float*)d_in[8 + i];
    P.Wtk    = (const float*)d_in[16];
    P.at     = (const float*)d_in[17];
    P.W      = (const float*)d_in[18];
    P.q_rela = (const float*)d_in[19];

    k_pre<<<NB_INIT + NB_HIST, 256>>>(P);                     // 0
    k_scan<<<SCAN_NBLK, 1024>>>();                            // 1
    k_fill<<<(TOTAL_EDGES + 255) / 256, 256>>>(P);            // 2

    for (int it = 0; it < 4; it++) {
        k_rowagg<<<(TOTAL_ROWS * 32 + 255) / 256, 256>>>();   // 3 on it=0
        k_trans<<<(TOTAL_ROWS + 127) / 128, 128>>>(P);        // 4
        k_agg<<<(OUT_ROWS * 2 + 255) / 256, 256>>>(P);        // 5
    }
    k_out<<<(OUT_ROWS * 50 + 255) / 256, 256>>>((float*)d_out);
}

// round 7
// speedup vs baseline: 3.5338x; 3.5338x over previous
#include <cuda_runtime.h>
#include <cuda_fp16.h>
#include <math.h>

namespace {

constexpr int DKP = 28;              // padded factor dim (25 -> 28)
constexpr int NDIM = 2 * DKP;        // 56 floats per node (fp32 master)
constexpr int HS   = 28;             // half2 stride per node in fp16 mirror
constexpr int TOTAL_NODES = 180000;  // 60000 + 30000 + 6*15000
constexpr int TOTAL_ROWS  = 270000;  // 60000 + 7*30000
constexpr int TOTAL_COLS  = 180000;  // 30000 + 60000 + 6*15000
constexpr int TOTAL_EDGES = 3800000; // 2*1e6 + 6*3e5
constexpr int OUT_ROWS = 90000;
constexpr int SCAN_ELEMS = 8192;     // per block (1024 thr x 8)
constexpr int SCAN_NBLK = (TOTAL_ROWS + SCAN_ELEMS - 1) / SCAN_ELEMS; // 33

__constant__ int c_EOFF[9] = {0,1000000,2000000,2300000,2600000,2900000,3200000,3500000,3800000};
__constant__ int c_ROFF[9] = {0,60000,90000,120000,150000,180000,210000,240000,270000};
__constant__ int c_COFF[9] = {0,30000,90000,105000,120000,135000,150000,165000,180000};
__constant__ int c_TOFF[9] = {0,60000,90000,105000,120000,135000,150000,165000,180000};
__constant__ int c_SRC[8]  = {0,1,1,1,1,1,1,1};
__constant__ int c_DST[8]  = {1,0,2,3,4,5,6,7};

__device__ float    g_emb [(size_t)TOTAL_NODES * NDIM + 16]; // fp32 master
__device__ unsigned g_embh[(size_t)TOTAL_NODES * HS];        // fp16 mirror: half2(k0[d],k1[d])
__device__ float    g_z   [(size_t)TOTAL_ROWS  * NDIM];      // transformed messages z'
__device__ float    g_p   [TOTAL_ROWS * 2];
__device__ __half   g_qh  [TOTAL_COLS * 2];                  // fp16 q, pair-packed
__device__ float    g_r   [TOTAL_ROWS * 2];
__device__ int      g_rowcnt[TOTAL_ROWS];
__device__ int      g_rowptr[TOTAL_ROWS + 1];
__device__ int      g_blocksum[SCAN_NBLK];
__device__ int      g_rank  [TOTAL_EDGES];
__device__ int      g_colidx[TOTAL_EDGES];

struct Ptrs {
    const int*   edge[8];
    const float* embin[8];
    const float* Wtk;
    const float* at;
    const float* W;
    const float* q_rela;
};

__device__ __forceinline__ int find_seg8(const int* off, int x) {
    int e = 0;
    #pragma unroll
    for (int i = 1; i < 8; i++) e += (x >= off[i]);
    return e;
}

__device__ __forceinline__ float fast_tanh(float x) {
    float y;
    asm("tanh.approx.f32 %0, %1;" : "=f"(y) : "f"(x));
    return y;
}

__device__ __forceinline__ float dot25(const float* v, const float* a) {
    float s = 0.f;
    #pragma unroll
    for (int d = 0; d < 25; d++) s += v[d] * __ldg(&a[d]);
    return s;
}

// write p (fp32) and q (fp16) for node (type t, local n, factor k)
__device__ __forceinline__ void write_pq(int t, int n, int k, const float* vec, const float* at) {
    if (t == 0) {
        g_p [(c_ROFF[0] + n) * 2 + k] = dot25(vec, at + (0 * 2 + k) * 50);
        g_qh[(c_COFF[1] + n) * 2 + k] = __float2half(dot25(vec, at + (1 * 2 + k) * 50 + 25));
    } else if (t == 1) {
        #pragma unroll
        for (int e = 1; e < 8; e++)
            g_p[(c_ROFF[e] + n) * 2 + k] = dot25(vec, at + (e * 2 + k) * 50);
        g_qh[(c_COFF[0] + n) * 2 + k] = __float2half(dot25(vec, at + (0 * 2 + k) * 50 + 25));
    } else {
        g_qh[(c_COFF[t] + n) * 2 + k] = __float2half(dot25(vec, at + (t * 2 + k) * 50 + 25));
    }
}

// fp16 mirror write: factor-k halves at node*56 + 2d + k  (== half2 lane d)
__device__ __forceinline__ void write_mirror(int node, int k, const float* vec) {
    __half* h = (__half*)g_embh;
    #pragma unroll
    for (int d = 0; d < 25; d++) h[(size_t)node * 2 * HS + 2 * d + k] = __float2half(vec[d]);
}

// ---------------- initial projection + fused p/q + mirror -------------------------
__global__ void __launch_bounds__(128) k_init(Ptrs P) {
    __shared__ float Wsh[2][2][50 * 25];   // [which-type][k][d*25+f]
    int base_slot = blockIdx.x * 128;
    int node0 = base_slot >> 1;
    int nlast = (base_slot + 127) >> 1;
    if (nlast > TOTAL_NODES - 1) nlast = TOTAL_NODES - 1;
    int t0 = find_seg8(c_TOFF, node0);
    int t1 = find_seg8(c_TOFF, nlast);
    for (int i = threadIdx.x; i < 2 * 50 * 25; i += 128) {
        Wsh[0][0][i] = P.Wtk[(size_t)t0 * 2 * 50 * 25 + i];
        Wsh[1][0][i] = P.Wtk[(size_t)t1 * 2 * 50 * 25 + i];
    }
    __syncthreads();
    int slot = base_slot + threadIdx.x;
    if (slot >= TOTAL_NODES * 2) return;
    int node = slot >> 1, k = slot & 1;
    int t = find_seg8(c_TOFF, node);
    int sel = (t == t0) ? 0 : 1;
    const float* x = P.embin[t] + (size_t)(node - c_TOFF[t]) * 50;
    const float* w = &Wsh[sel][k][0];
    float out[25];
    #pragma unroll
    for (int f = 0; f < 25; f++) out[f] = 0.f;
    for (int d = 0; d < 50; d++) {
        float xd = __ldg(&x[d]);
        #pragma unroll
        for (int f = 0; f < 25; f++) out[f] += xd * w[d * 25 + f];
    }
    float nrm = 0.f;
    #pragma unroll
    for (int f = 0; f < 25; f++) {
        float s = out[f];
        s = (s >= 0.f) ? s : 0.2f * s;
        out[f] = s;
        nrm += s * s;
    }
    float inv = 1.f / fmaxf(sqrtf(nrm), 1e-12f);
    #pragma unroll
    for (int f = 0; f < 25; f++) out[f] *= inv;
    float* dst = g_emb + (size_t)node * NDIM + k * DKP;
    #pragma unroll
    for (int f = 0; f < 25; f++) dst[f] = out[f];
    dst[25] = 0.f; dst[26] = 0.f; dst[27] = 0.f;
    write_mirror(node, k, out);
    write_pq(t, node - c_TOFF[t], k, out, P.at);
}

// ---------------- zero rowcnt -----------------------------------------------------
__global__ void k_zeroscratch() {
    int i = blockIdx.x * blockDim.x + threadIdx.x;
    if (i < TOTAL_ROWS) g_rowcnt[i] = 0;
}

// ---------------- CSR build: hist also records each edge's within-row rank --------
__global__ void k_hist(Ptrs P) {
    int j = blockIdx.x * blockDim.x + threadIdx.x;
    if (j >= TOTAL_EDGES) return;
    int e = find_seg8(c_EOFF, j);
    int le = j - c_EOFF[e];
    int u = P.edge[e][le];
    g_rank[j] = atomicAdd(&g_rowcnt[c_ROFF[e] + u], 1);
}

// 3-kernel scan, 8 elems/thread
__global__ void __launch_bounds__(1024) k_scanA() {
    __shared__ int sh[1024];
    int bid = blockIdx.x, tid = threadIdx.x;
    int base = bid * SCAN_ELEMS + tid * 8;
    int v[8];
    #pragma unroll
    for (int u = 0; u < 8; u++) {
        int i = base + u;
        v[u] = (i < TOTAL_ROWS) ? g_rowcnt[i] : 0;
    }
    int tsum = 0;
    #pragma unroll
    for (int u = 0; u < 8; u++) tsum += v[u];
    sh[tid] = tsum;
    __syncthreads();
    #pragma unroll
    for (int off = 1; off < 1024; off <<= 1) {
        int t = (tid >= off) ? sh[tid - off] : 0;
        __syncthreads();
        sh[tid] += t;
        __syncthreads();
    }
    int p = sh[tid] - tsum;   // local exclusive
    #pragma unroll
    for (int u = 0; u < 8; u++) {
        int i = base + u;
        if (i < TOTAL_ROWS) g_rowptr[i] = p;
        p += v[u];
    }
    if (tid == 1023) g_blocksum[bid] = sh[1023];
}

__global__ void k_scanB() {
    // 64 threads scan 33 block sums (exclusive)
    int tid = threadIdx.x;
    int v = (tid < SCAN_NBLK) ? g_blocksum[tid] : 0;
    int s = v;
    #pragma unroll
    for (int off = 1; off < 64; off <<= 1) {
        int t = __shfl_up_sync(0xffffffffu, s, off);
        if ((tid & 31) >= off) s += t;
    }
    __shared__ int w0tot;
    if (tid == 31) w0tot = s;
    __syncthreads();
    if (tid >= 32) s += w0tot;
    if (tid < SCAN_NBLK) g_blocksum[tid] = s - v;
}

__global__ void k_scanC() {
    int i = blockIdx.x * blockDim.x + threadIdx.x;
    if (i < TOTAL_ROWS) g_rowptr[i] += g_blocksum[i >> 13];
    if (i == 0) g_rowptr[TOTAL_ROWS] = TOTAL_EDGES;
}

__global__ void k_fill(Ptrs P) {
    int j = blockIdx.x * blockDim.x + threadIdx.x;
    if (j >= TOTAL_EDGES) return;
    int e = find_seg8(c_EOFF, j);
    int le = j - c_EOFF[e];
    int E = c_EOFF[e + 1] - c_EOFF[e];
    const int* ed = P.edge[e];
    int u = ed[le], c = ed[E + le];
    int row = c_ROFF[e] + u;
    g_colidx[g_rowptr[row] + g_rank[j]] = c;
}

// ---------------- fused: score+softmax+aggregate+transform (warp/row) -------------
// R5 structure; ONLY change: (w,c) staged in shared once per chunk -> LDS.64
// broadcasts in the inner loop instead of 2 SHFLs per edge.
__global__ void __launch_bounds__(256) k_rowtrans(Ptrs P) {
    __shared__ float Ws[625];
    __shared__ float zsh[8][56];     // per-warp staged lrelu(z): [0..24]=k0, [28..52]=k1
    __shared__ float2 wc[8][32];     // per-warp staged (weight, colidx)
    for (int i = threadIdx.x; i < 625; i += 256) Ws[i] = P.W[i];
    __syncthreads();

    int row  = (blockIdx.x * 256 + threadIdx.x) >> 5;
    int lane = threadIdx.x & 31;
    int w_id = (threadIdx.x >> 5);
    bool active = (row < TOTAL_ROWS);
    int e = 0, base = 0, deg = 0, coff = 0, nbase = 0;
    float2 pv = make_float2(0.f, 0.f);
    if (active) {
        e = find_seg8(c_ROFF, row);
        base = g_rowptr[row];
        deg  = g_rowptr[row + 1] - base;
        coff  = c_COFF[e];
        nbase = c_TOFF[c_DST[e]];
        pv = ((const float2*)g_p)[row];
    }
    int dlane = (lane < 25) ? lane : 24;   // lanes 25-31 duplicate lane 24 (discarded)

    float s = 0.f;
    float accA = 0.f, accB = 0.f;          // lane d: factor0[d], factor1[d]

    const unsigned* qh32 = (const unsigned*)g_qh;
    for (int i0 = 0; i0 < deg; i0 += 32) {
        int i = i0 + lane;
        int c = 0; float w = 0.f;
        if (i < deg) {
            c = __ldg(&g_colidx[base + i]);
            unsigned qraw = __ldg(&qh32[coff + c]);
            float2 qv = __half22float2(*(const __half2*)&qraw);
            float v = 0.5f * (fmaxf(pv.x + qv.x, 0.f) + fmaxf(pv.y + qv.y, 0.f));
            w = __expf(v);
            s += w;
        }
        wc[w_id][lane] = make_float2(w, __int_as_float(c));
        __syncwarp();
        int nn = deg - i0; if (nn > 32) nn = 32;
        int nn4 = (nn + 3) & ~3;           // padded lanes: w=0, c=0 -> harmless
        for (int j = 0; j < nn4; j += 4) {
            float2 e0 = wc[w_id][j + 0];
            float2 e1 = wc[w_id][j + 1];
            float2 e2 = wc[w_id][j + 2];
            float2 e3 = wc[w_id][j + 3];
            unsigned h0 = __ldg(&g_embh[(size_t)(nbase + __float_as_int(e0.y)) * HS + dlane]);
            unsigned h1 = __ldg(&g_embh[(size_t)(nbase + __float_as_int(e1.y)) * HS + dlane]);
            unsigned h2 = __ldg(&g_embh[(size_t)(nbase + __float_as_int(e2.y)) * HS + dlane]);
            unsigned h3 = __ldg(&g_embh[(size_t)(nbase + __float_as_int(e3.y)) * HS + dlane]);
            float2 f0 = __half22float2(*(const __half2*)&h0);
            float2 f1 = __half22float2(*(const __half2*)&h1);
            float2 f2 = __half22float2(*(const __half2*)&h2);
            float2 f3 = __half22float2(*(const __half2*)&h3);
            accA += e0.x * f0.x; accB += e0.x * f0.y;
            accA += e1.x * f1.x; accB += e1.x * f1.y;
            accA += e2.x * f2.x; accB += e2.x * f2.y;
            accA += e3.x * f3.x; accB += e3.x * f3.y;
        }
        __syncwarp();
    }
    #pragma unroll
    for (int off = 16; off; off >>= 1)
        s += __shfl_xor_sync(0xffffffffu, s, off);
    float invS = (deg > 0) ? (1.f / s) : 0.f;

    if (lane < 25) {
        float zx = accA * invS;
        float zy = accB * invS;
        zsh[w_id][lane]      = (zx >= 0.f) ? zx : 0.2f * zx;
        zsh[w_id][28 + lane] = (zy >= 0.f) ? zy : 0.2f * zy;
    }
    __syncwarp();

    // transform: lane f<25 computes out[k][f] = sum_d zsh[k][d]*W[d][f]
    float out0 = 0.f, out1 = 0.f;
    if (lane < 25) {
        const float* z0 = &zsh[w_id][0];
        const float* z1 = &zsh[w_id][28];
        #pragma unroll
        for (int d = 0; d < 25; d++) {
            float wdf = Ws[d * 25 + lane];
            out0 += z0[d] * wdf;
            out1 += z1[d] * wdf;
        }
    }
    float qrf = (active && lane < 25) ? __ldg(&P.q_rela[e * 25 + lane]) : 0.f;
    float p0 = fast_tanh(out0) * qrf;
    float p1 = fast_tanh(out1) * qrf;
    if (lane >= 25) { p0 = 0.f; p1 = 0.f; }
    #pragma unroll
    for (int off = 16; off; off >>= 1) {
        p0 += __shfl_xor_sync(0xffffffffu, p0, off);
        p1 += __shfl_xor_sync(0xffffffffu, p1, off);
    }
    if (active) {
        if (lane == 0) {
            float mm = fmaxf(p0, p1);
            float e0 = __expf(p0 - mm), e1 = __expf(p1 - mm);
            float inv = 1.f / (e0 + e1);
            ((float2*)g_r)[row] = make_float2(e0 * inv, e1 * inv);
        }
        float* zr = g_z + (size_t)row * NDIM;
        if (lane < 25) {
            zr[lane] = out0;
            zr[DKP + lane] = out1;
        }
    }
}

// ---------------- ego aggregation + l2 normalize + p/q + mirror refresh -----------
__global__ void __launch_bounds__(256) k_agg(Ptrs P) {
    int slot = blockIdx.x * 256 + threadIdx.x;
    if (slot >= OUT_ROWS * 2) return;
    int node = slot >> 1, k = slot & 1;
    float acc[25];
    float* er = g_emb + (size_t)node * NDIM + k * DKP;
    #pragma unroll
    for (int d = 0; d < 25; d++) acc[d] = er[d];
    if (node < 60000) {                 // type 0: relation 0 only
        float r = g_r[node * 2 + k];
        const float* zz = g_z + (size_t)node * NDIM + k * DKP;
        #pragma unroll
        for (int d = 0; d < 25; d++) acc[d] += r * zz[d];
    } else {                            // type 1: relations 1..7
        int n = node - 60000;
        #pragma unroll
        for (int e = 1; e < 8; e++) {
            int row = c_ROFF[e] + n;
            float r = g_r[row * 2 + k];
            const float* zz = g_z + (size_t)row * NDIM + k * DKP;
            #pragma unroll
            for (int d = 0; d < 25; d++) acc[d] += r * zz[d];
        }
    }
    float nrm = 0.f;
    #pragma unroll
    for (int d = 0; d < 25; d++) nrm += acc[d] * acc[d];
    float inv = 1.f / fmaxf(sqrtf(nrm), 1e-12f);
    #pragma unroll
    for (int d = 0; d < 25; d++) acc[d] *= inv;
    #pragma unroll
    for (int d = 0; d < 25; d++) er[d] = acc[d];
    write_mirror(node, k, acc);
    int t = (node < 60000) ? 0 : 1;
    write_pq(t, (t == 0) ? node : node - 60000, k, acc, P.at);
}

// ---------------- output: [n, k*25+d] for user then item --------------------------
__global__ void k_out(float* __restrict__ out) {
    int idx = blockIdx.x * blockDim.x + threadIdx.x;
    if (idx >= OUT_ROWS * 50) return;
    int r = idx / 50, c = idx - r * 50;
    int k = c / 25, d = c - k * 25;
    out[idx] = g_emb[(size_t)r * NDIM + k * DKP + d];
}

} // anonymous namespace

extern "C" void kernel_launch(void* const* d_in, const int* in_sizes, int n_in,
                              void* d_out, int out_size) {
    Ptrs P;
    for (int i = 0; i < 8; i++) P.edge[i]  = (const int*)d_in[i];
    for (int i = 0; i < 8; i++) P.embin[i] = (const float*)d_in[8 + i];
    P.Wtk    = (const float*)d_in[16];
    P.at     = (const float*)d_in[17];
    P.W      = (const float*)d_in[18];
    P.q_rela = (const float*)d_in[19];

    k_init<<<(TOTAL_NODES * 2 + 127) / 128, 128>>>(P);
    k_zeroscratch<<<(TOTAL_ROWS + 255) / 256, 256>>>();
    k_hist<<<(TOTAL_EDGES + 255) / 256, 256>>>(P);
    k_scanA<<<SCAN_NBLK, 1024>>>();
    k_scanB<<<1, 64>>>();
    k_scanC<<<(TOTAL_ROWS + 255) / 256, 256>>>();
    k_fill<<<(TOTAL_EDGES + 255) / 256, 256>>>(P);

    for (int it = 0; it < 4; it++) {
        k_rowtrans<<<(TOTAL_ROWS * 32 + 255) / 256, 256>>>(P);
        k_agg<<<(OUT_ROWS * 2 + 255) / 256, 256>>>(P);
    }
    k_out<<<(OUT_ROWS * 50 + 255) / 256, 256>>>((float*)d_out);
}

// round 12
// speedup vs baseline: 3.6389x; 1.0297x over previous
#include <cuda_runtime.h>
#include <cuda_fp16.h>
#include <math.h>

namespace {

constexpr int DKP = 28;              // padded factor dim (25 -> 28)
constexpr int NDIM = 2 * DKP;        // 56 floats per node (fp32 master)
constexpr int HS   = 28;             // half2 stride per node in fp16 mirror
constexpr int TOTAL_NODES = 180000;  // 60000 + 30000 + 6*15000
constexpr int TOTAL_ROWS  = 270000;  // 60000 + 7*30000
constexpr int TOTAL_COLS  = 180000;  // 30000 + 60000 + 6*15000
constexpr int TOTAL_EDGES = 3800000; // 2*1e6 + 6*3e5
constexpr int OUT_ROWS = 90000;
constexpr int SCAN_ELEMS = 8192;     // per block (1024 thr x 8)
constexpr int SCAN_NBLK = (TOTAL_ROWS + SCAN_ELEMS - 1) / SCAN_ELEMS; // 33

__constant__ int c_EOFF[9] = {0,1000000,2000000,2300000,2600000,2900000,3200000,3500000,3800000};
__constant__ int c_ROFF[9] = {0,60000,90000,120000,150000,180000,210000,240000,270000};
__constant__ int c_COFF[9] = {0,30000,90000,105000,120000,135000,150000,165000,180000};
__constant__ int c_TOFF[9] = {0,60000,90000,105000,120000,135000,150000,165000,180000};
__constant__ int c_SRC[8]  = {0,1,1,1,1,1,1,1};
__constant__ int c_DST[8]  = {1,0,2,3,4,5,6,7};

__device__ float    g_emb [(size_t)TOTAL_NODES * NDIM + 16]; // fp32 master
__device__ unsigned g_embh[(size_t)TOTAL_NODES * HS];        // fp16 mirror: half2(k0[d],k1[d])
__device__ float    g_z   [(size_t)TOTAL_ROWS  * NDIM];      // transformed messages z'
__device__ float    g_p   [TOTAL_ROWS * 2];
__device__ __half   g_qh  [TOTAL_COLS * 2];                  // fp16 q, pair-packed
__device__ float    g_r   [TOTAL_ROWS * 2];
__device__ int      g_rowcnt[TOTAL_ROWS];
__device__ int      g_rowptr[TOTAL_ROWS + 1];
__device__ int      g_blocksum[SCAN_NBLK];
__device__ int      g_rank  [TOTAL_EDGES];
__device__ int      g_colidx[TOTAL_EDGES];

struct Ptrs {
    const int*   edge[8];
    const float* embin[8];
    const float* Wtk;
    const float* at;
    const float* W;
    const float* q_rela;
};

__device__ __forceinline__ int find_seg8(const int* off, int x) {
    int e = 0;
    #pragma unroll
    for (int i = 1; i < 8; i++) e += (x >= off[i]);
    return e;
}

__device__ __forceinline__ float fast_tanh(float x) {
    float y;
    asm("tanh.approx.f32 %0, %1;" : "=f"(y) : "f"(x));
    return y;
}

__device__ __forceinline__ float dot25(const float* v, const float* a) {
    float s = 0.f;
    #pragma unroll
    for (int d = 0; d < 25; d++) s += v[d] * __ldg(&a[d]);
    return s;
}

// thread-level p/q write (used by k_init only)
__device__ __forceinline__ void write_pq(int t, int n, int k, const float* vec, const float* at) {
    if (t == 0) {
        g_p [(c_ROFF[0] + n) * 2 + k] = dot25(vec, at + (0 * 2 + k) * 50);
        g_qh[(c_COFF[1] + n) * 2 + k] = __float2half(dot25(vec, at + (1 * 2 + k) * 50 + 25));
    } else if (t == 1) {
        #pragma unroll
        for (int e = 1; e < 8; e++)
            g_p[(c_ROFF[e] + n) * 2 + k] = dot25(vec, at + (e * 2 + k) * 50);
        g_qh[(c_COFF[0] + n) * 2 + k] = __float2half(dot25(vec, at + (0 * 2 + k) * 50 + 25));
    } else {
        g_qh[(c_COFF[t] + n) * 2 + k] = __float2half(dot25(vec, at + (t * 2 + k) * 50 + 25));
    }
}

__device__ __forceinline__ void write_mirror(int node, int k, const float* vec) {
    __half* h = (__half*)g_embh;
    #pragma unroll
    for (int d = 0; d < 25; d++) h[(size_t)node * 2 * HS + 2 * d + k] = __float2half(vec[d]);
}

__device__ __forceinline__ float warp_sum(float v) {
    #pragma unroll
    for (int off = 16; off; off >>= 1)
        v += __shfl_xor_sync(0xffffffffu, v, off);
    return v;
}

__device__ __forceinline__ unsigned pack_half2(float a, float b) {
    __half2 h = __float22half2_rn(make_float2(a, b));
    return *reinterpret_cast<unsigned*>(&h);
}

// ---------------- initial projection + fused p/q + mirror -------------------------
__global__ void __launch_bounds__(128) k_init(Ptrs P) {
    __shared__ float Wsh[2][2][50 * 25];   // [which-type][k][d*25+f]
    int base_slot = blockIdx.x * 128;
    int node0 = base_slot >> 1;
    int nlast = (base_slot + 127) >> 1;
    if (nlast > TOTAL_NODES - 1) nlast = TOTAL_NODES - 1;
    int t0 = find_seg8(c_TOFF, node0);
    int t1 = find_seg8(c_TOFF, nlast);
    for (int i = threadIdx.x; i < 2 * 50 * 25; i += 128) {
        Wsh[0][0][i] = P.Wtk[(size_t)t0 * 2 * 50 * 25 + i];
        Wsh[1][0][i] = P.Wtk[(size_t)t1 * 2 * 50 * 25 + i];
    }
    __syncthreads();
    int slot = base_slot + threadIdx.x;
    if (slot >= TOTAL_NODES * 2) return;
    int node = slot >> 1, k = slot & 1;
    int t = find_seg8(c_TOFF, node);
    int sel = (t == t0) ? 0 : 1;
    const float* x = P.embin[t] + (size_t)(node - c_TOFF[t]) * 50;
    const float* w = &Wsh[sel][k][0];
    float out[25];
    #pragma unroll
    for (int f = 0; f < 25; f++) out[f] = 0.f;
    for (int d = 0; d < 50; d++) {
        float xd = __ldg(&x[d]);
        #pragma unroll
        for (int f = 0; f < 25; f++) out[f] += xd * w[d * 25 + f];
    }
    float nrm = 0.f;
    #pragma unroll
    for (int f = 0; f < 25; f++) {
        float s = out[f];
        s = (s >= 0.f) ? s : 0.2f * s;
        out[f] = s;
        nrm += s * s;
    }
    float inv = 1.f / fmaxf(sqrtf(nrm), 1e-12f);
    #pragma unroll
    for (int f = 0; f < 25; f++) out[f] *= inv;
    float* dst = g_emb + (size_t)node * NDIM + k * DKP;
    #pragma unroll
    for (int f = 0; f < 25; f++) dst[f] = out[f];
    dst[25] = 0.f; dst[26] = 0.f; dst[27] = 0.f;
    write_mirror(node, k, out);
    write_pq(t, node - c_TOFF[t], k, out, P.at);
}

// ---------------- zero rowcnt -----------------------------------------------------
__global__ void k_zeroscratch() {
    int i = blockIdx.x * blockDim.x + threadIdx.x;
    if (i < TOTAL_ROWS) g_rowcnt[i] = 0;
}

// ---------------- CSR build: hist also records each edge's within-row rank --------
__global__ void k_hist(Ptrs P) {
    int j = blockIdx.x * blockDim.x + threadIdx.x;
    if (j >= TOTAL_EDGES) return;
    int e = find_seg8(c_EOFF, j);
    int le = j - c_EOFF[e];
    int u = P.edge[e][le];
    g_rank[j] = atomicAdd(&g_rowcnt[c_ROFF[e] + u], 1);
}

// 3-kernel scan, 8 elems/thread
__global__ void __launch_bounds__(1024) k_scanA() {
    __shared__ int sh[1024];
    int bid = blockIdx.x, tid = threadIdx.x;
    int base = bid * SCAN_ELEMS + tid * 8;
    int v[8];
    #pragma unroll
    for (int u = 0; u < 8; u++) {
        int i = base + u;
        v[u] = (i < TOTAL_ROWS) ? g_rowcnt[i] : 0;
    }
    int tsum = 0;
    #pragma unroll
    for (int u = 0; u < 8; u++) tsum += v[u];
    sh[tid] = tsum;
    __syncthreads();
    #pragma unroll
    for (int off = 1; off < 1024; off <<= 1) {
        int t = (tid >= off) ? sh[tid - off] : 0;
        __syncthreads();
        sh[tid] += t;
        __syncthreads();
    }
    int p = sh[tid] - tsum;   // local exclusive
    #pragma unroll
    for (int u = 0; u < 8; u++) {
        int i = base + u;
        if (i < TOTAL_ROWS) g_rowptr[i] = p;
        p += v[u];
    }
    if (tid == 1023) g_blocksum[bid] = sh[1023];
}

__global__ void k_scanB() {
    // 64 threads scan 33 block sums (exclusive)
    int tid = threadIdx.x;
    int v = (tid < SCAN_NBLK) ? g_blocksum[tid] : 0;
    int s = v;
    #pragma unroll
    for (int off = 1; off < 64; off <<= 1) {
        int t = __shfl_up_sync(0xffffffffu, s, off);
        if ((tid & 31) >= off) s += t;
    }
    __shared__ int w0tot;
    if (tid == 31) w0tot = s;
    __syncthreads();
    if (tid >= 32) s += w0tot;
    if (tid < SCAN_NBLK) g_blocksum[tid] = s - v;
}

__global__ void k_scanC() {
    int i = blockIdx.x * blockDim.x + threadIdx.x;
    if (i < TOTAL_ROWS) g_rowptr[i] += g_blocksum[i >> 13];
    if (i == 0) g_rowptr[TOTAL_ROWS] = TOTAL_EDGES;
}

__global__ void k_fill(Ptrs P) {
    int j = blockIdx.x * blockDim.x + threadIdx.x;
    if (j >= TOTAL_EDGES) return;
    int e = find_seg8(c_EOFF, j);
    int le = j - c_EOFF[e];
    int E = c_EOFF[e + 1] - c_EOFF[e];
    const int* ed = P.edge[e];
    int u = ed[le], c = ed[E + le];
    int row = c_ROFF[e] + u;
    g_colidx[g_rowptr[row] + g_rank[j]] = c;
}

// ---------------- fused: score+softmax+aggregate+transform (warp/row) -------------
__global__ void __launch_bounds__(256) k_rowtrans(Ptrs P) {
    __shared__ float Ws[625];
    __shared__ float zsh[8][56];     // per-warp staged lrelu(z): [0..24]=k0, [28..52]=k1
    __shared__ float2 wc[8][32];     // per-warp staged (weight, colidx)
    for (int i = threadIdx.x; i < 625; i += 256) Ws[i] = P.W[i];
    __syncthreads();

    int row  = (blockIdx.x * 256 + threadIdx.x) >> 5;
    int lane = threadIdx.x & 31;
    int w_id = (threadIdx.x >> 5);
    bool active = (row < TOTAL_ROWS);
    int e = 0, base = 0, deg = 0, coff = 0, nbase = 0;
    float2 pv = make_float2(0.f, 0.f);
    if (active) {
        e = find_seg8(c_ROFF, row);
        base = g_rowptr[row];
        deg  = g_rowptr[row + 1] - base;
        coff  = c_COFF[e];
        nbase = c_TOFF[c_DST[e]];
        pv = ((const float2*)g_p)[row];
    }
    int dlane = (lane < 25) ? lane : 24;   // lanes 25-31 duplicate lane 24 (discarded)

    float s = 0.f;
    float accA = 0.f, accB = 0.f;          // lane d: factor0[d], factor1[d]

    const unsigned* qh32 = (const unsigned*)g_qh;
    for (int i0 = 0; i0 < deg; i0 += 32) {
        int i = i0 + lane;
        int c = 0; float w = 0.f;
        if (i < deg) {
            c = __ldg(&g_colidx[base + i]);
            unsigned qraw = __ldg(&qh32[coff + c]);
            float2 qv = __half22float2(*(const __half2*)&qraw);
            float v = 0.5f * (fmaxf(pv.x + qv.x, 0.f) + fmaxf(pv.y + qv.y, 0.f));
            w = __expf(v);
            s += w;
        }
        wc[w_id][lane] = make_float2(w, __int_as_float(c));
        __syncwarp();
        int nn = deg - i0; if (nn > 32) nn = 32;
        int nn4 = (nn + 3) & ~3;           // padded lanes: w=0, c=0 -> harmless
        for (int j = 0; j < nn4; j += 4) {
            float2 e0 = wc[w_id][j + 0];
            float2 e1 = wc[w_id][j + 1];
            float2 e2 = wc[w_id][j + 2];
            float2 e3 = wc[w_id][j + 3];
            unsigned h0 = __ldg(&g_embh[(size_t)(nbase + __float_as_int(e0.y)) * HS + dlane]);
            unsigned h1 = __ldg(&g_embh[(size_t)(nbase + __float_as_int(e1.y)) * HS + dlane]);
            unsigned h2 = __ldg(&g_embh[(size_t)(nbase + __float_as_int(e2.y)) * HS + dlane]);
            unsigned h3 = __ldg(&g_embh[(size_t)(nbase + __float_as_int(e3.y)) * HS + dlane]);
            float2 f0 = __half22float2(*(const __half2*)&h0);
            float2 f1 = __half22float2(*(const __half2*)&h1);
            float2 f2 = __half22float2(*(const __half2*)&h2);
            float2 f3 = __half22float2(*(const __half2*)&h3);
            accA += e0.x * f0.x; accB += e0.x * f0.y;
            accA += e1.x * f1.x; accB += e1.x * f1.y;
            accA += e2.x * f2.x; accB += e2.x * f2.y;
            accA += e3.x * f3.x; accB += e3.x * f3.y;
        }
        __syncwarp();
    }
    s = warp_sum(s);
    float invS = (deg > 0) ? (1.f / s) : 0.f;

    if (lane < 25) {
        float zx = accA * invS;
        float zy = accB * invS;
        zsh[w_id][lane]      = (zx >= 0.f) ? zx : 0.2f * zx;
        zsh[w_id][28 + lane] = (zy >= 0.f) ? zy : 0.2f * zy;
    }
    __syncwarp();

    float out0 = 0.f, out1 = 0.f;
    if (lane < 25) {
        const float* z0 = &zsh[w_id][0];
        const float* z1 = &zsh[w_id][28];
        #pragma unroll
        for (int d = 0; d < 25; d++) {
            float wdf = Ws[d * 25 + lane];
            out0 += z0[d] * wdf;
            out1 += z1[d] * wdf;
        }
    }
    float qrf = (active && lane < 25) ? __ldg(&P.q_rela[e * 25 + lane]) : 0.f;
    float p0 = fast_tanh(out0) * qrf;
    float p1 = fast_tanh(out1) * qrf;
    if (lane >= 25) { p0 = 0.f; p1 = 0.f; }
    p0 = warp_sum(p0);
    p1 = warp_sum(p1);
    if (active) {
        if (lane == 0) {
            float mm = fmaxf(p0, p1);
            float e0 = __expf(p0 - mm), e1 = __expf(p1 - mm);
            float inv = 1.f / (e0 + e1);
            ((float2*)g_r)[row] = make_float2(e0 * inv, e1 * inv);
        }
        float* zr = g_z + (size_t)row * NDIM;
        if (lane < 25) {
            zr[lane] = out0;
            zr[DKP + lane] = out1;
        }
    }
}

// ---------------- warp-per-node ego aggregation + normalize + p/q + mirror --------
// Lane d<25 owns dim d for both factors. All emb/z accesses coalesced (4 sectors
// per warp instruction); r loads broadcast; p/q dots = lane FFMA + butterfly.
__global__ void __launch_bounds__(256) k_agg(Ptrs P) {
    int node = (blockIdx.x * 256 + threadIdx.x) >> 5;
    int lane = threadIdx.x & 31;
    if (node >= OUT_ROWS) return;
    bool ld = (lane < 25);
    float* er = g_emb + (size_t)node * NDIM;
    float a0 = 0.f, a1 = 0.f;
    if (ld) { a0 = er[lane]; a1 = er[DKP + lane]; }
    if (node < 60000) {                 // type 0: relation 0 only
        float2 r = ((const float2*)g_r)[node];
        const float* zz = g_z + (size_t)node * NDIM;
        if (ld) { a0 += r.x * zz[lane]; a1 += r.y * zz[DKP + lane]; }
    } else {                            // type 1: relations 1..7
        int n = node - 60000;
        #pragma unroll
        for (int e = 1; e < 8; e++) {
            int row = c_ROFF[e] + n;
            float2 r = ((const float2*)g_r)[row];
            const float* zz = g_z + (size_t)row * NDIM;
            if (ld) { a0 += r.x * zz[lane]; a1 += r.y * zz[DKP + lane]; }
        }
    }
    float n0 = warp_sum(a0 * a0);
    float n1 = warp_sum(a1 * a1);
    a0 *= 1.f / fmaxf(sqrtf(n0), 1e-12f);
    a1 *= 1.f / fmaxf(sqrtf(n1), 1e-12f);
    if (ld) {
        er[lane] = a0;
        er[DKP + lane] = a1;
        g_embh[(size_t)node * HS + lane] = pack_half2(a0, a1);
    }
    // p/q dots: type0 -> p(rel0), q(rel1); type1 -> p(rel1..7), q(rel0)
    const float* at = P.at;
    if (node < 60000) {
        int n = node;
        #pragma unroll
        for (int k = 0; k < 2; k++) {
            float ak = k ? a1 : a0;
            float dp = warp_sum(ld ? ak * __ldg(&at[(0 * 2 + k) * 50 + lane]) : 0.f);
            float dq = warp_sum(ld ? ak * __ldg(&at[(1 * 2 + k) * 50 + 25 + lane]) : 0.f);
            if (lane == 0) {
                g_p [(c_ROFF[0] + n) * 2 + k] = dp;
                g_qh[(c_COFF[1] + n) * 2 + k] = __float2half(dq);
            }
        }
    } else {
        int n = node - 60000;
        #pragma unroll
        for (int k = 0; k < 2; k++) {
            float ak = k ? a1 : a0;
            #pragma unroll
            for (int e = 1; e < 8; e++) {
                float dp = warp_sum(ld ? ak * __ldg(&at[(e * 2 + k) * 50 + lane]) : 0.f);
                if (lane == 0) g_p[(c_ROFF[e] + n) * 2 + k] = dp;
            }
            float dq = warp_sum(ld ? ak * __ldg(&at[(0 * 2 + k) * 50 + 25 + lane]) : 0.f);
            if (lane == 0) g_qh[(c_COFF[0] + n) * 2 + k] = __float2half(dq);
        }
    }
}

// ---------------- output: [n, k*25+d] for user then item --------------------------
__global__ void k_out(float* __restrict__ out) {
    int idx = blockIdx.x * blockDim.x + threadIdx.x;
    if (idx >= OUT_ROWS * 50) return;
    int r = idx / 50, c = idx - r * 50;
    int k = c / 25, d = c - k * 25;
    out[idx] = g_emb[(size_t)r * NDIM + k * DKP + d];
}

} // anonymous namespace

extern "C" void kernel_launch(void* const* d_in, const int* in_sizes, int n_in,
                              void* d_out, int out_size) {
    Ptrs P;
    for (int i = 0; i < 8; i++) P.edge[i]  = (const int*)d_in[i];
    for (int i = 0; i < 8; i++) P.embin[i] = (const float*)d_in[8 + i];
    P.Wtk    = (const float*)d_in[16];
    P.at     = (const float*)d_in[17];
    P.W      = (const float*)d_in[18];
    P.q_rela = (const float*)d_in[19];

    k_init<<<(TOTAL_NODES * 2 + 127) / 128, 128>>>(P);
    k_zeroscratch<<<(TOTAL_ROWS + 255) / 256, 256>>>();
    k_hist<<<(TOTAL_EDGES + 255) / 256, 256>>>(P);
    k_scanA<<<SCAN_NBLK, 1024>>>();
    k_scanB<<<1, 64>>>();
    k_scanC<<<(TOTAL_ROWS + 255) / 256, 256>>>();
    k_fill<<<(TOTAL_EDGES + 255) / 256, 256>>>(P);

    for (int it = 0; it < 4; it++) {
        k_rowtrans<<<(TOTAL_ROWS * 32 + 255) / 256, 256>>>(P);
        k_agg<<<(OUT_ROWS * 32 + 255) / 256, 256>>>(P);
    }
    k_out<<<(OUT_ROWS * 50 + 255) / 256, 256>>>((float*)d_out);
}

// round 13
// speedup vs baseline: 3.7614x; 1.0337x over previous
#include <cuda_runtime.h>
#include <cuda_fp16.h>
#include <math.h>

namespace {

constexpr int DKP = 28;              // padded factor dim (25 -> 28), fp32 master
constexpr int NDIM = 2 * DKP;        // 56 floats per node (fp32 master)
constexpr int HS   = 32;             // half2 stride per node in fp16 mirror (128B aligned)
constexpr int TOTAL_NODES = 180000;  // 60000 + 30000 + 6*15000
constexpr int TOTAL_ROWS  = 270000;  // 60000 + 7*30000
constexpr int TOTAL_COLS  = 180000;  // 30000 + 60000 + 6*15000
constexpr int TOTAL_EDGES = 3800000; // 2*1e6 + 6*3e5
constexpr int OUT_ROWS = 90000;
constexpr int SCAN_ELEMS = 8192;     // per block (1024 thr x 8)
constexpr int SCAN_NBLK = (TOTAL_ROWS + SCAN_ELEMS - 1) / SCAN_ELEMS; // 33

__constant__ int c_EOFF[9] = {0,1000000,2000000,2300000,2600000,2900000,3200000,3500000,3800000};
__constant__ int c_ROFF[9] = {0,60000,90000,120000,150000,180000,210000,240000,270000};
__constant__ int c_COFF[9] = {0,30000,90000,105000,120000,135000,150000,165000,180000};
__constant__ int c_TOFF[9] = {0,60000,90000,105000,120000,135000,150000,165000,180000};
__constant__ int c_SRC[8]  = {0,1,1,1,1,1,1,1};
__constant__ int c_DST[8]  = {1,0,2,3,4,5,6,7};

__device__ float    g_emb [(size_t)TOTAL_NODES * NDIM + 16]; // fp32 master
__device__ unsigned g_embh[(size_t)TOTAL_NODES * HS];        // fp16 mirror: half2(k0[d],k1[d]), 128B rows
__device__ float    g_z   [(size_t)TOTAL_ROWS  * NDIM];      // transformed messages z'
__device__ float    g_p   [TOTAL_ROWS * 2];
__device__ __half   g_qh  [TOTAL_COLS * 2];                  // fp16 q, pair-packed
__device__ float    g_r   [TOTAL_ROWS * 2];
__device__ int      g_rowcnt[TOTAL_ROWS];        // re-zeroed by k_fill (invariant)
__device__ int      g_rowptr[TOTAL_ROWS + 1];
__device__ int      g_blocksum[SCAN_NBLK];
__device__ int      g_rank  [TOTAL_EDGES];
__device__ int      g_colidx[TOTAL_EDGES];       // pre-scaled: (nbase+c)*HS
__device__ int      g_colq  [TOTAL_EDGES];       // pre-offset: coff+c

struct Ptrs {
    const int*   edge[8];
    const float* embin[8];
    const float* Wtk;
    const float* at;
    const float* W;
    const float* q_rela;
};

__device__ __forceinline__ int find_seg8(const int* off, int x) {
    int e = 0;
    #pragma unroll
    for (int i = 1; i < 8; i++) e += (x >= off[i]);
    return e;
}

__device__ __forceinline__ float fast_tanh(float x) {
    float y;
    asm("tanh.approx.f32 %0, %1;" : "=f"(y) : "f"(x));
    return y;
}

__device__ __forceinline__ float dot25(const float* v, const float* a) {
    float s = 0.f;
    #pragma unroll
    for (int d = 0; d < 25; d++) s += v[d] * __ldg(&a[d]);
    return s;
}

// thread-level p/q write (used by k_init only)
__device__ __forceinline__ void write_pq(int t, int n, int k, const float* vec, const float* at) {
    if (t == 0) {
        g_p [(c_ROFF[0] + n) * 2 + k] = dot25(vec, at + (0 * 2 + k) * 50);
        g_qh[(c_COFF[1] + n) * 2 + k] = __float2half(dot25(vec, at + (1 * 2 + k) * 50 + 25));
    } else if (t == 1) {
        #pragma unroll
        for (int e = 1; e < 8; e++)
            g_p[(c_ROFF[e] + n) * 2 + k] = dot25(vec, at + (e * 2 + k) * 50);
        g_qh[(c_COFF[0] + n) * 2 + k] = __float2half(dot25(vec, at + (0 * 2 + k) * 50 + 25));
    } else {
        g_qh[(c_COFF[t] + n) * 2 + k] = __float2half(dot25(vec, at + (t * 2 + k) * 50 + 25));
    }
}

__device__ __forceinline__ void write_mirror(int node, int k, const float* vec) {
    __half* h = (__half*)g_embh;
    #pragma unroll
    for (int d = 0; d < 25; d++) h[(size_t)node * 2 * HS + 2 * d + k] = __float2half(vec[d]);
}

__device__ __forceinline__ float warp_sum(float v) {
    #pragma unroll
    for (int off = 16; off; off >>= 1)
        v += __shfl_xor_sync(0xffffffffu, v, off);
    return v;
}

__device__ __forceinline__ unsigned pack_half2(float a, float b) {
    __half2 h = __float22half2_rn(make_float2(a, b));
    return *reinterpret_cast<unsigned*>(&h);
}

// ---------------- initial projection + fused p/q + mirror -------------------------
__global__ void __launch_bounds__(128) k_init(Ptrs P) {
    __shared__ float Wsh[2][2][50 * 25];   // [which-type][k][d*25+f]
    int base_slot = blockIdx.x * 128;
    int node0 = base_slot >> 1;
    int nlast = (base_slot + 127) >> 1;
    if (nlast > TOTAL_NODES - 1) nlast = TOTAL_NODES - 1;
    int t0 = find_seg8(c_TOFF, node0);
    int t1 = find_seg8(c_TOFF, nlast);
    for (int i = threadIdx.x; i < 2 * 50 * 25; i += 128) {
        Wsh[0][0][i] = P.Wtk[(size_t)t0 * 2 * 50 * 25 + i];
        Wsh[1][0][i] = P.Wtk[(size_t)t1 * 2 * 50 * 25 + i];
    }
    __syncthreads();
    int slot = base_slot + threadIdx.x;
    if (slot >= TOTAL_NODES * 2) return;
    int node = slot >> 1, k = slot & 1;
    int t = find_seg8(c_TOFF, node);
    int sel = (t == t0) ? 0 : 1;
    const float* x = P.embin[t] + (size_t)(node - c_TOFF[t]) * 50;
    const float* w = &Wsh[sel][k][0];
    float out[25];
    #pragma unroll
    for (int f = 0; f < 25; f++) out[f] = 0.f;
    for (int d = 0; d < 50; d++) {
        float xd = __ldg(&x[d]);
        #pragma unroll
        for (int f = 0; f < 25; f++) out[f] += xd * w[d * 25 + f];
    }
    float nrm = 0.f;
    #pragma unroll
    for (int f = 0; f < 25; f++) {
        float s = out[f];
        s = (s >= 0.f) ? s : 0.2f * s;
        out[f] = s;
        nrm += s * s;
    }
    float inv = 1.f / fmaxf(sqrtf(nrm), 1e-12f);
    #pragma unroll
    for (int f = 0; f < 25; f++) out[f] *= inv;
    float* dst = g_emb + (size_t)node * NDIM + k * DKP;
    #pragma unroll
    for (int f = 0; f < 25; f++) dst[f] = out[f];
    dst[25] = 0.f; dst[26] = 0.f; dst[27] = 0.f;
    write_mirror(node, k, out);
    write_pq(t, node - c_TOFF[t], k, out, P.at);
}

// ---------------- CSR build: hist also records each edge's within-row rank --------
__global__ void k_hist(Ptrs P) {
    int j = blockIdx.x * blockDim.x + threadIdx.x;
    if (j >= TOTAL_EDGES) return;
    int e = find_seg8(c_EOFF, j);
    int le = j - c_EOFF[e];
    int u = P.edge[e][le];
    g_rank[j] = atomicAdd(&g_rowcnt[c_ROFF[e] + u], 1);
}

// 3-kernel scan, 8 elems/thread
__global__ void __launch_bounds__(1024) k_scanA() {
    __shared__ int sh[1024];
    int bid = blockIdx.x, tid = threadIdx.x;
    int base = bid * SCAN_ELEMS + tid * 8;
    int v[8];
    #pragma unroll
    for (int u = 0; u < 8; u++) {
        int i = base + u;
        v[u] = (i < TOTAL_ROWS) ? g_rowcnt[i] : 0;
    }
    int tsum = 0;
    #pragma unroll
    for (int u = 0; u < 8; u++) tsum += v[u];
    sh[tid] = tsum;
    __syncthreads();
    #pragma unroll
    for (int off = 1; off < 1024; off <<= 1) {
        int t = (tid >= off) ? sh[tid - off] : 0;
        __syncthreads();
        sh[tid] += t;
        __syncthreads();
    }
    int p = sh[tid] - tsum;   // local exclusive
    #pragma unroll
    for (int u = 0; u < 8; u++) {
        int i = base + u;
        if (i < TOTAL_ROWS) g_rowptr[i] = p;
        p += v[u];
    }
    if (tid == 1023) g_blocksum[bid] = sh[1023];
}

__global__ void k_scanB() {
    // 64 threads scan 33 block sums (exclusive)
    int tid = threadIdx.x;
    int v = (tid < SCAN_NBLK) ? g_blocksum[tid] : 0;
    int s = v;
    #pragma unroll
    for (int off = 1; off < 64; off <<= 1) {
        int t = __shfl_up_sync(0xffffffffu, s, off);
        if ((tid & 31) >= off) s += t;
    }
    __shared__ int w0tot;
    if (tid == 31) w0tot = s;
    __syncthreads();
    if (tid >= 32) s += w0tot;
    if (tid < SCAN_NBLK) g_blocksum[tid] = s - v;
}

__global__ void k_scanC() {
    int i = blockIdx.x * blockDim.x + threadIdx.x;
    if (i < TOTAL_ROWS) g_rowptr[i] += g_blocksum[i >> 13];
    if (i == 0) g_rowptr[TOTAL_ROWS] = TOTAL_EDGES;
}

// fill colidx (pre-scaled) + colq; re-zero rowcnt for the next launch (invariant:
// rowcnt is zero before every k_hist — true on first call since globals init to 0)
__global__ void k_fill(Ptrs P) {
    int j = blockIdx.x * blockDim.x + threadIdx.x;
    if (j < TOTAL_ROWS) g_rowcnt[j] = 0;
    if (j >= TOTAL_EDGES) return;
    int e = find_seg8(c_EOFF, j);
    int le = j - c_EOFF[e];
    int E = c_EOFF[e + 1] - c_EOFF[e];
    const int* ed = P.edge[e];
    int u = ed[le], c = ed[E + le];
    int row = c_ROFF[e] + u;
    int pos = g_rowptr[row] + g_rank[j];
    g_colidx[pos] = (c_TOFF[c_DST[e]] + c) * HS;   // pre-scaled mirror index
    g_colq[pos]   = c_COFF[e] + c;                 // pre-offset q index
}

// ---------------- fused: score+softmax+aggregate+transform (warp/row) -------------
__global__ void __launch_bounds__(256) k_rowtrans(Ptrs P) {
    __shared__ float Ws[625];
    __shared__ float zsh[8][56];     // per-warp staged lrelu(z): [0..24]=k0, [28..52]=k1
    __shared__ float2 wc[8][32];     // per-warp staged (weight, scaled colidx)
    for (int i = threadIdx.x; i < 625; i += 256) Ws[i] = P.W[i];
    __syncthreads();

    int row  = (blockIdx.x * 256 + threadIdx.x) >> 5;
    int lane = threadIdx.x & 31;
    int w_id = (threadIdx.x >> 5);
    bool active = (row < TOTAL_ROWS);
    int e = 0, base = 0, deg = 0;
    float2 pv = make_float2(0.f, 0.f);
    if (active) {
        e = find_seg8(c_ROFF, row);
        base = g_rowptr[row];
        deg  = g_rowptr[row + 1] - base;
        pv = ((const float2*)g_p)[row];
    }
    int dlane = (lane < 25) ? lane : 24;   // lanes 25-31 duplicate lane 24 (discarded)

    float s = 0.f;
    float accA = 0.f, accB = 0.f;          // lane d: factor0[d], factor1[d]

    const unsigned* qh32 = (const unsigned*)g_qh;
    for (int i0 = 0; i0 < deg; i0 += 32) {
        int i = i0 + lane;
        int cs = 0; float w = 0.f;
        if (i < deg) {
            cs = __ldg(&g_colidx[base + i]);
            int cq = __ldg(&g_colq[base + i]);
            unsigned qraw = __ldg(&qh32[cq]);
            float2 qv = __half22float2(*(const __half2*)&qraw);
            float v = 0.5f * (fmaxf(pv.x + qv.x, 0.f) + fmaxf(pv.y + qv.y, 0.f));
            w = __expf(v);
            s += w;
        }
        wc[w_id][lane] = make_float2(w, __int_as_float(cs));
        __syncwarp();
        int nn = deg - i0; if (nn > 32) nn = 32;
        int nn4 = (nn + 3) & ~3;           // padded lanes: w=0, cs=0 -> harmless
        for (int j = 0; j < nn4; j += 4) {
            float2 e0 = wc[w_id][j + 0];
            float2 e1 = wc[w_id][j + 1];
            float2 e2 = wc[w_id][j + 2];
            float2 e3 = wc[w_id][j + 3];
            unsigned h0 = __ldg(&g_embh[__float_as_int(e0.y) + dlane]);
            unsigned h1 = __ldg(&g_embh[__float_as_int(e1.y) + dlane]);
            unsigned h2 = __ldg(&g_embh[__float_as_int(e2.y) + dlane]);
            unsigned h3 = __ldg(&g_embh[__float_as_int(e3.y) + dlane]);
            float2 f0 = __half22float2(*(const __half2*)&h0);
            float2 f1 = __half22float2(*(const __half2*)&h1);
            float2 f2 = __half22float2(*(const __half2*)&h2);
            float2 f3 = __half22float2(*(const __half2*)&h3);
            accA += e0.x * f0.x; accB += e0.x * f0.y;
            accA += e1.x * f1.x; accB += e1.x * f1.y;
            accA += e2.x * f2.x; accB += e2.x * f2.y;
            accA += e3.x * f3.x; accB += e3.x * f3.y;
        }
        __syncwarp();
    }
    s = warp_sum(s);
    float invS = (deg > 0) ? (1.f / s) : 0.f;

    if (lane < 25) {
        float zx = accA * invS;
        float zy = accB * invS;
        zsh[w_id][lane]      = (zx >= 0.f) ? zx : 0.2f * zx;
        zsh[w_id][28 + lane] = (zy >= 0.f) ? zy : 0.2f * zy;
    }
    __syncwarp();

    float out0 = 0.f, out1 = 0.f;
    if (lane < 25) {
        const float* z0 = &zsh[w_id][0];
        const float* z1 = &zsh[w_id][28];
        #pragma unroll
        for (int d = 0; d < 25; d++) {
            float wdf = Ws[d * 25 + lane];
            out0 += z0[d] * wdf;
            out1 += z1[d] * wdf;
        }
    }
    float qrf = (active && lane < 25) ? __ldg(&P.q_rela[e * 25 + lane]) : 0.f;
    float p0 = fast_tanh(out0) * qrf;
    float p1 = fast_tanh(out1) * qrf;
    if (lane >= 25) { p0 = 0.f; p1 = 0.f; }
    p0 = warp_sum(p0);
    p1 = warp_sum(p1);
    if (active) {
        if (lane == 0) {
            float mm = fmaxf(p0, p1);
            float e0 = __expf(p0 - mm), e1 = __expf(p1 - mm);
            float inv = 1.f / (e0 + e1);
            ((float2*)g_r)[row] = make_float2(e0 * inv, e1 * inv);
        }
        float* zr = g_z + (size_t)row * NDIM;
        if (lane < 25) {
            zr[lane] = out0;
            zr[DKP + lane] = out1;
        }
    }
}

// ---------------- warp-per-node ego aggregation + normalize + p/q + mirror --------
__global__ void __launch_bounds__(256) k_agg(Ptrs P) {
    int node = (blockIdx.x * 256 + threadIdx.x) >> 5;
    int lane = threadIdx.x & 31;
    if (node >= OUT_ROWS) return;
    bool ld = (lane < 25);
    float* er = g_emb + (size_t)node * NDIM;
    float a0 = 0.f, a1 = 0.f;
    if (ld) { a0 = er[lane]; a1 = er[DKP + lane]; }
    if (node < 60000) {                 // type 0: relation 0 only
        float2 r = ((const float2*)g_r)[node];
        const float* zz = g_z + (size_t)node * NDIM;
        if (ld) { a0 += r.x * zz[lane]; a1 += r.y * zz[DKP + lane]; }
    } else {                            // type 1: relations 1..7
        int n = node - 60000;
        #pragma unroll
        for (int e = 1; e < 8; e++) {
            int row = c_ROFF[e] + n;
            float2 r = ((const float2*)g_r)[row];
            const float* zz = g_z + (size_t)row * NDIM;
            if (ld) { a0 += r.x * zz[lane]; a1 += r.y * zz[DKP + lane]; }
        }
    }
    float n0 = warp_sum(a0 * a0);
    float n1 = warp_sum(a1 * a1);
    a0 *= 1.f / fmaxf(sqrtf(n0), 1e-12f);
    a1 *= 1.f / fmaxf(sqrtf(n1), 1e-12f);
    if (ld) {
        er[lane] = a0;
        er[DKP + lane] = a1;
        g_embh[(size_t)node * HS + lane] = pack_half2(a0, a1);
    }
    // p/q dots: type0 -> p(rel0), q(rel1); type1 -> p(rel1..7), q(rel0)
    const float* at = P.at;
    if (node < 60000) {
        int n = node;
        #pragma unroll
        for (int k = 0; k < 2; k++) {
            float ak = k ? a1 : a0;
            float dp = warp_sum(ld ? ak * __ldg(&at[(0 * 2 + k) * 50 + lane]) : 0.f);
            float dq = warp_sum(ld ? ak * __ldg(&at[(1 * 2 + k) * 50 + 25 + lane]) : 0.f);
            if (lane == 0) {
                g_p [(c_ROFF[0] + n) * 2 + k] = dp;
                g_qh[(c_COFF[1] + n) * 2 + k] = __float2half(dq);
            }
        }
    } else {
        int n = node - 60000;
        #pragma unroll
        for (int k = 0; k < 2; k++) {
            float ak = k ? a1 : a0;
            #pragma unroll
            for (int e = 1; e < 8; e++) {
                float dp = warp_sum(ld ? ak * __ldg(&at[(e * 2 + k) * 50 + lane]) : 0.f);
                if (lane == 0) g_p[(c_ROFF[e] + n) * 2 + k] = dp;
            }
            float dq = warp_sum(ld ? ak * __ldg(&at[(0 * 2 + k) * 50 + 25 + lane]) : 0.f);
            if (lane == 0) g_qh[(c_COFF[0] + n) * 2 + k] = __float2half(dq);
        }
    }
}

// ---------------- output: [n, k*25+d] for user then item --------------------------
__global__ void k_out(float* __restrict__ out) {
    int idx = blockIdx.x * blockDim.x + threadIdx.x;
    if (idx >= OUT_ROWS * 50) return;
    int r = idx / 50, c = idx - r * 50;
    int k = c / 25, d = c - k * 25;
    out[idx] = g_emb[(size_t)r * NDIM + k * DKP + d];
}

} // anonymous namespace

extern "C" void kernel_launch(void* const* d_in, const int* in_sizes, int n_in,
                              void* d_out, int out_size) {
    Ptrs P;
    for (int i = 0; i < 8; i++) P.edge[i]  = (const int*)d_in[i];
    for (int i = 0; i < 8; i++) P.embin[i] = (const float*)d_in[8 + i];
    P.Wtk    = (const float*)d_in[16];
    P.at     = (const float*)d_in[17];
    P.W      = (const float*)d_in[18];
    P.q_rela = (const float*)d_in[19];

    k_init<<<(TOTAL_NODES * 2 + 127) / 128, 128>>>(P);
    k_hist<<<(TOTAL_EDGES + 255) / 256, 256>>>(P);
    k_scanA<<<SCAN_NBLK, 1024>>>();
    k_scanB<<<1, 64>>>();
    k_scanC<<<(TOTAL_ROWS + 255) / 256, 256>>>();
    k_fill<<<(TOTAL_EDGES + 255) / 256, 256>>>(P);

    for (int it = 0; it < 4; it++) {
        k_rowtrans<<<(TOTAL_ROWS * 32 + 255) / 256, 256>>>(P);
        k_agg<<<(OUT_ROWS * 32 + 255) / 256, 256>>>(P);
    }
    k_out<<<(OUT_ROWS * 50 + 255) / 256, 256>>>((float*)d_out);
}

// round 14
// speedup vs baseline: 3.9714x; 1.0558x over previous
#include <cuda_runtime.h>
#include <cuda_fp16.h>
#include <math.h>

namespace {

constexpr int DKP = 28;              // padded factor dim (25 -> 28), fp32 master
constexpr int NDIM = 2 * DKP;        // 56 floats per node (fp32 master)
constexpr int HS   = 32;             // half2 stride per node in fp16 mirror (128B aligned)
constexpr int TOTAL_NODES = 180000;  // 60000 + 30000 + 6*15000
constexpr int TOTAL_ROWS  = 270000;  // 60000 + 7*30000
constexpr int TOTAL_COLS  = 180000;  // 30000 + 60000 + 6*15000
constexpr int TOTAL_EDGES = 3800000; // 2*1e6 + 6*3e5
constexpr int OUT_ROWS = 90000;
constexpr int SCAN_ELEMS = 8192;     // per block (1024 thr x 8)
constexpr int SCAN_NBLK = (TOTAL_ROWS + SCAN_ELEMS - 1) / SCAN_ELEMS; // 33

__constant__ int c_EOFF[9] = {0,1000000,2000000,2300000,2600000,2900000,3200000,3500000,3800000};
__constant__ int c_ROFF[9] = {0,60000,90000,120000,150000,180000,210000,240000,270000};
__constant__ int c_COFF[9] = {0,30000,90000,105000,120000,135000,150000,165000,180000};
__constant__ int c_TOFF[9] = {0,60000,90000,105000,120000,135000,150000,165000,180000};
__constant__ int c_SRC[8]  = {0,1,1,1,1,1,1,1};
__constant__ int c_DST[8]  = {1,0,2,3,4,5,6,7};

__device__ float    g_emb [(size_t)TOTAL_NODES * NDIM + 16]; // fp32 master
__device__ unsigned g_embh[(size_t)TOTAL_NODES * HS];        // fp16 mirror: half2(k0[d],k1[d]), 128B rows
__device__ float    g_z   [(size_t)TOTAL_ROWS  * NDIM];      // transformed messages z'
__device__ float    g_p   [TOTAL_ROWS * 2];
__device__ __half   g_qh  [TOTAL_COLS * 2];                  // fp16 q, pair-packed
__device__ float    g_r   [TOTAL_ROWS * 2];
__device__ int      g_rowcnt[TOTAL_ROWS];        // re-zeroed by k_fill (invariant)
__device__ int      g_rowptr[TOTAL_ROWS + 1];
__device__ int      g_blocksum[SCAN_NBLK];
__device__ int      g_rank  [TOTAL_EDGES];
__device__ int2     g_cc    [TOTAL_EDGES];       // (pre-scaled mirror idx, pre-offset q idx)

struct Ptrs {
    const int*   edge[8];
    const float* embin[8];
    const float* Wtk;
    const float* at;
    const float* W;
    const float* q_rela;
};

__device__ __forceinline__ int find_seg8(const int* off, int x) {
    int e = 0;
    #pragma unroll
    for (int i = 1; i < 8; i++) e += (x >= off[i]);
    return e;
}

__device__ __forceinline__ float fast_tanh(float x) {
    float y;
    asm("tanh.approx.f32 %0, %1;" : "=f"(y) : "f"(x));
    return y;
}

__device__ __forceinline__ float dot25(const float* v, const float* a) {
    float s = 0.f;
    #pragma unroll
    for (int d = 0; d < 25; d++) s += v[d] * __ldg(&a[d]);
    return s;
}

// thread-level p/q write (used by k_init only)
__device__ __forceinline__ void write_pq(int t, int n, int k, const float* vec, const float* at) {
    if (t == 0) {
        g_p [(c_ROFF[0] + n) * 2 + k] = dot25(vec, at + (0 * 2 + k) * 50);
        g_qh[(c_COFF[1] + n) * 2 + k] = __float2half(dot25(vec, at + (1 * 2 + k) * 50 + 25));
    } else if (t == 1) {
        #pragma unroll
        for (int e = 1; e < 8; e++)
            g_p[(c_ROFF[e] + n) * 2 + k] = dot25(vec, at + (e * 2 + k) * 50);
        g_qh[(c_COFF[0] + n) * 2 + k] = __float2half(dot25(vec, at + (0 * 2 + k) * 50 + 25));
    } else {
        g_qh[(c_COFF[t] + n) * 2 + k] = __float2half(dot25(vec, at + (t * 2 + k) * 50 + 25));
    }
}

__device__ __forceinline__ void write_mirror(int node, int k, const float* vec) {
    __half* h = (__half*)g_embh;
    #pragma unroll
    for (int d = 0; d < 25; d++) h[(size_t)node * 2 * HS + 2 * d + k] = __float2half(vec[d]);
}

__device__ __forceinline__ float warp_sum(float v) {
    #pragma unroll
    for (int off = 16; off; off >>= 1)
        v += __shfl_xor_sync(0xffffffffu, v, off);
    return v;
}

__device__ __forceinline__ unsigned pack_half2(float a, float b) {
    __half2 h = __float22half2_rn(make_float2(a, b));
    return *reinterpret_cast<unsigned*>(&h);
}

// ---------------- initial projection + fused p/q + mirror -------------------------
__global__ void __launch_bounds__(128) k_init(Ptrs P) {
    __shared__ float Wsh[2][2][50 * 25];   // [which-type][k][d*25+f]
    int base_slot = blockIdx.x * 128;
    int node0 = base_slot >> 1;
    int nlast = (base_slot + 127) >> 1;
    if (nlast > TOTAL_NODES - 1) nlast = TOTAL_NODES - 1;
    int t0 = find_seg8(c_TOFF, node0);
    int t1 = find_seg8(c_TOFF, nlast);
    for (int i = threadIdx.x; i < 2 * 50 * 25; i += 128) {
        Wsh[0][0][i] = P.Wtk[(size_t)t0 * 2 * 50 * 25 + i];
        Wsh[1][0][i] = P.Wtk[(size_t)t1 * 2 * 50 * 25 + i];
    }
    __syncthreads();
    int slot = base_slot + threadIdx.x;
    if (slot >= TOTAL_NODES * 2) return;
    int node = slot >> 1, k = slot & 1;
    int t = find_seg8(c_TOFF, node);
    int sel = (t == t0) ? 0 : 1;
    const float* x = P.embin[t] + (size_t)(node - c_TOFF[t]) * 50;
    const float* w = &Wsh[sel][k][0];
    float out[25];
    #pragma unroll
    for (int f = 0; f < 25; f++) out[f] = 0.f;
    for (int d = 0; d < 50; d++) {
        float xd = __ldg(&x[d]);
        #pragma unroll
        for (int f = 0; f < 25; f++) out[f] += xd * w[d * 25 + f];
    }
    float nrm = 0.f;
    #pragma unroll
    for (int f = 0; f < 25; f++) {
        float s = out[f];
        s = (s >= 0.f) ? s : 0.2f * s;
        out[f] = s;
        nrm += s * s;
    }
    float inv = 1.f / fmaxf(sqrtf(nrm), 1e-12f);
    #pragma unroll
    for (int f = 0; f < 25; f++) out[f] *= inv;
    float* dst = g_emb + (size_t)node * NDIM + k * DKP;
    #pragma unroll
    for (int f = 0; f < 25; f++) dst[f] = out[f];
    dst[25] = 0.f; dst[26] = 0.f; dst[27] = 0.f;
    write_mirror(node, k, out);
    write_pq(t, node - c_TOFF[t], k, out, P.at);
}

// ---------------- CSR build: hist also records each edge's within-row rank --------
__global__ void k_hist(Ptrs P) {
    int j = blockIdx.x * blockDim.x + threadIdx.x;
    if (j >= TOTAL_EDGES) return;
    int e = find_seg8(c_EOFF, j);
    int le = j - c_EOFF[e];
    int u = P.edge[e][le];
    g_rank[j] = atomicAdd(&g_rowcnt[c_ROFF[e] + u], 1);
}

// 3-kernel scan, 8 elems/thread
__global__ void __launch_bounds__(1024) k_scanA() {
    __shared__ int sh[1024];
    int bid = blockIdx.x, tid = threadIdx.x;
    int base = bid * SCAN_ELEMS + tid * 8;
    int v[8];
    #pragma unroll
    for (int u = 0; u < 8; u++) {
        int i = base + u;
        v[u] = (i < TOTAL_ROWS) ? g_rowcnt[i] : 0;
    }
    int tsum = 0;
    #pragma unroll
    for (int u = 0; u < 8; u++) tsum += v[u];
    sh[tid] = tsum;
    __syncthreads();
    #pragma unroll
    for (int off = 1; off < 1024; off <<= 1) {
        int t = (tid >= off) ? sh[tid - off] : 0;
        __syncthreads();
        sh[tid] += t;
        __syncthreads();
    }
    int p = sh[tid] - tsum;   // local exclusive
    #pragma unroll
    for (int u = 0; u < 8; u++) {
        int i = base + u;
        if (i < TOTAL_ROWS) g_rowptr[i] = p;
        p += v[u];
    }
    if (tid == 1023) g_blocksum[bid] = sh[1023];
}

__global__ void k_scanB() {
    // 64 threads scan 33 block sums (exclusive)
    int tid = threadIdx.x;
    int v = (tid < SCAN_NBLK) ? g_blocksum[tid] : 0;
    int s = v;
    #pragma unroll
    for (int off = 1; off < 64; off <<= 1) {
        int t = __shfl_up_sync(0xffffffffu, s, off);
        if ((tid & 31) >= off) s += t;
    }
    __shared__ int w0tot;
    if (tid == 31) w0tot = s;
    __syncthreads();
    if (tid >= 32) s += w0tot;
    if (tid < SCAN_NBLK) g_blocksum[tid] = s - v;
}

__global__ void k_scanC() {
    int i = blockIdx.x * blockDim.x + threadIdx.x;
    if (i < TOTAL_ROWS) g_rowptr[i] += g_blocksum[i >> 13];
    if (i == 0) g_rowptr[TOTAL_ROWS] = TOTAL_EDGES;
}

// fill packed (cs,cq); re-zero rowcnt for the next launch (invariant: rowcnt is
// zero before every k_hist — true on first call since globals init to 0)
__global__ void k_fill(Ptrs P) {
    int j = blockIdx.x * blockDim.x + threadIdx.x;
    if (j < TOTAL_ROWS) g_rowcnt[j] = 0;
    if (j >= TOTAL_EDGES) return;
    int e = find_seg8(c_EOFF, j);
    int le = j - c_EOFF[e];
    int E = c_EOFF[e + 1] - c_EOFF[e];
    const int* ed = P.edge[e];
    int u = ed[le], c = ed[E + le];
    int row = c_ROFF[e] + u;
    int pos = g_rowptr[row] + g_rank[j];
    g_cc[pos] = make_int2((c_TOFF[c_DST[e]] + c) * HS, c_COFF[e] + c);
}

// ---------------- fused: score+softmax+aggregate+transform (warp/row) -------------
__global__ void __launch_bounds__(256) k_rowtrans(Ptrs P) {
    __shared__ float Ws[625];
    __shared__ float zsh[8][56];     // per-warp staged lrelu(z): [0..24]=k0, [28..52]=k1
    __shared__ float2 wc[8][32];     // per-warp staged (weight, scaled colidx)
    for (int i = threadIdx.x; i < 625; i += 256) Ws[i] = P.W[i];
    __syncthreads();

    int row  = (blockIdx.x * 256 + threadIdx.x) >> 5;
    int lane = threadIdx.x & 31;
    int w_id = (threadIdx.x >> 5);
    bool active = (row < TOTAL_ROWS);
    int e = 0, base = 0, deg = 0;
    float2 pv = make_float2(0.f, 0.f);
    if (active) {
        e = find_seg8(c_ROFF, row);
        base = g_rowptr[row];
        deg  = g_rowptr[row + 1] - base;
        pv = ((const float2*)g_p)[row];
    }
    int dlane = (lane < 25) ? lane : 24;   // lanes 25-31 duplicate lane 24 (discarded)

    float s = 0.f;
    float accA = 0.f, accB = 0.f;          // lane d: factor0[d], factor1[d]

    const unsigned* qh32 = (const unsigned*)g_qh;
    for (int i0 = 0; i0 < deg; i0 += 32) {
        int i = i0 + lane;
        int cs = 0; float w = 0.f;
        if (i < deg) {
            int2 cc = __ldg(&g_cc[base + i]);
            cs = cc.x;
            unsigned qraw = __ldg(&qh32[cc.y]);
            float2 qv = __half22float2(*(const __half2*)&qraw);
            float v = 0.5f * (fmaxf(pv.x + qv.x, 0.f) + fmaxf(pv.y + qv.y, 0.f));
            w = __expf(v);
            s += w;
        }
        wc[w_id][lane] = make_float2(w, __int_as_float(cs));
        __syncwarp();
        int nn = deg - i0; if (nn > 32) nn = 32;
        int nn4 = (nn + 3) & ~3;           // padded lanes: w=0, cs=0 -> harmless
        for (int j = 0; j < nn4; j += 4) {
            float2 e0 = wc[w_id][j + 0];
            float2 e1 = wc[w_id][j + 1];
            float2 e2 = wc[w_id][j + 2];
            float2 e3 = wc[w_id][j + 3];
            unsigned h0 = __ldg(&g_embh[__float_as_int(e0.y) + dlane]);
            unsigned h1 = __ldg(&g_embh[__float_as_int(e1.y) + dlane]);
            unsigned h2 = __ldg(&g_embh[__float_as_int(e2.y) + dlane]);
            unsigned h3 = __ldg(&g_embh[__float_as_int(e3.y) + dlane]);
            float2 f0 = __half22float2(*(const __half2*)&h0);
            float2 f1 = __half22float2(*(const __half2*)&h1);
            float2 f2 = __half22float2(*(const __half2*)&h2);
            float2 f3 = __half22float2(*(const __half2*)&h3);
            accA += e0.x * f0.x; accB += e0.x * f0.y;
            accA += e1.x * f1.x; accB += e1.x * f1.y;
            accA += e2.x * f2.x; accB += e2.x * f2.y;
            accA += e3.x * f3.x; accB += e3.x * f3.y;
        }
        __syncwarp();
    }
    s = warp_sum(s);
    float invS = (deg > 0) ? (1.f / s) : 0.f;

    if (lane < 25) {
        float zx = accA * invS;
        float zy = accB * invS;
        zsh[w_id][lane]      = (zx >= 0.f) ? zx : 0.2f * zx;
        zsh[w_id][28 + lane] = (zy >= 0.f) ? zy : 0.2f * zy;
    }
    __syncwarp();

    float out0 = 0.f, out1 = 0.f;
    if (lane < 25) {
        const float* z0 = &zsh[w_id][0];
        const float* z1 = &zsh[w_id][28];
        #pragma unroll
        for (int d = 0; d < 25; d++) {
            float wdf = Ws[d * 25 + lane];
            out0 += z0[d] * wdf;
            out1 += z1[d] * wdf;
        }
    }
    float qrf = (active && lane < 25) ? __ldg(&P.q_rela[e * 25 + lane]) : 0.f;
    float p0 = fast_tanh(out0) * qrf;
    float p1 = fast_tanh(out1) * qrf;
    if (lane >= 25) { p0 = 0.f; p1 = 0.f; }
    p0 = warp_sum(p0);
    p1 = warp_sum(p1);
    if (active) {
        if (lane == 0) {
            float mm = fmaxf(p0, p1);
            float e0 = __expf(p0 - mm), e1 = __expf(p1 - mm);
            float inv = 1.f / (e0 + e1);
            ((float2*)g_r)[row] = make_float2(e0 * inv, e1 * inv);
        }
        float* zr = g_z + (size_t)row * NDIM;
        if (lane < 25) {
            zr[lane] = out0;
            zr[DKP + lane] = out1;
        }
    }
}

// ---------------- warp-per-node ego aggregation + normalize -----------------------
// Non-last iters: update g_emb + mirror + p/q. Last iter: write d_out directly
// (k_init fully rewrites emb/mirror/p/q each launch, so skipping them is safe).
__global__ void __launch_bounds__(256) k_agg(Ptrs P, float* __restrict__ out, int last) {
    int node = (blockIdx.x * 256 + threadIdx.x) >> 5;
    int lane = threadIdx.x & 31;
    if (node >= OUT_ROWS) return;
    bool ld = (lane < 25);
    float* er = g_emb + (size_t)node * NDIM;
    float a0 = 0.f, a1 = 0.f;
    if (ld) { a0 = er[lane]; a1 = er[DKP + lane]; }
    if (node < 60000) {                 // type 0: relation 0 only
        float2 r = ((const float2*)g_r)[node];
        const float* zz = g_z + (size_t)node * NDIM;
        if (ld) { a0 += r.x * zz[lane]; a1 += r.y * zz[DKP + lane]; }
    } else {                            // type 1: relations 1..7
        int n = node - 60000;
        #pragma unroll
        for (int e = 1; e < 8; e++) {
            int row = c_ROFF[e] + n;
            float2 r = ((const float2*)g_r)[row];
            const float* zz = g_z + (size_t)row * NDIM;
            if (ld) { a0 += r.x * zz[lane]; a1 += r.y * zz[DKP + lane]; }
        }
    }
    float n0 = warp_sum(a0 * a0);
    float n1 = warp_sum(a1 * a1);
    a0 *= 1.f / fmaxf(sqrtf(n0), 1e-12f);
    a1 *= 1.f / fmaxf(sqrtf(n1), 1e-12f);

    if (last) {
        if (ld) {
            out[(size_t)node * 50 + lane]      = a0;
            out[(size_t)node * 50 + 25 + lane] = a1;
        }
        return;
    }

    if (ld) {
        er[lane] = a0;
        er[DKP + lane] = a1;
        g_embh[(size_t)node * HS + lane] = pack_half2(a0, a1);
    }
    // p/q dots: type0 -> p(rel0), q(rel1); type1 -> p(rel1..7), q(rel0)
    const float* at = P.at;
    if (node < 60000) {
        int n = node;
        #pragma unroll
        for (int k = 0; k < 2; k++) {
            float ak = k ? a1 : a0;
            float dp = warp_sum(ld ? ak * __ldg(&at[(0 * 2 + k) * 50 + lane]) : 0.f);
            float dq = warp_sum(ld ? ak * __ldg(&at[(1 * 2 + k) * 50 + 25 + lane]) : 0.f);
            if (lane == 0) {
                g_p [(c_ROFF[0] + n) * 2 + k] = dp;
                g_qh[(c_COFF[1] + n) * 2 + k] = __float2half(dq);
            }
        }
    } else {
        int n = node - 60000;
        #pragma unroll
        for (int k = 0; k < 2; k++) {
            float ak = k ? a1 : a0;
            #pragma unroll
            for (int e = 1; e < 8; e++) {
                float dp = warp_sum(ld ? ak * __ldg(&at[(e * 2 + k) * 50 + lane]) : 0.f);
                if (lane == 0) g_p[(c_ROFF[e] + n) * 2 + k] = dp;
            }
            float dq = warp_sum(ld ? ak * __ldg(&at[(0 * 2 + k) * 50 + 25 + lane]) : 0.f);
            if (lane == 0) g_qh[(c_COFF[0] + n) * 2 + k] = __float2half(dq);
        }
    }
}

} // anonymous namespace

extern "C" void kernel_launch(void* const* d_in, const int* in_sizes, int n_in,
                              void* d_out, int out_size) {
    Ptrs P;
    for (int i = 0; i < 8; i++) P.edge[i]  = (const int*)d_in[i];
    for (int i = 0; i < 8; i++) P.embin[i] = (const float*)d_in[8 + i];
    P.Wtk    = (const float*)d_in[16];
    P.at     = (const float*)d_in[17];
    P.W      = (const float*)d_in[18];
    P.q_rela = (const float*)d_in[19];

    k_init<<<(TOTAL_NODES * 2 + 127) / 128, 128>>>(P);
    k_hist<<<(TOTAL_EDGES + 255) / 256, 256>>>(P);
    k_scanA<<<SCAN_NBLK, 1024>>>();
    k_scanB<<<1, 64>>>();
    k_scanC<<<(TOTAL_ROWS + 255) / 256, 256>>>();
    k_fill<<<(TOTAL_EDGES + 255) / 256, 256>>>(P);

    for (int it = 0; it < 4; it++) {
        k_rowtrans<<<(TOTAL_ROWS * 32 + 255) / 256, 256>>>(P);
        k_agg<<<(OUT_ROWS * 32 + 255) / 256, 256>>>(P, (float*)d_out, it == 3);
    }
}